// round 1
// baseline (speedup 1.0000x reference)
#include <cuda_runtime.h>

#define NN   100000
#define EE   1600000
#define NADJ 4
#define DD   64

// ---------------- device scratch (static globals; no allocs allowed) ------
__device__ __align__(16) float  g_h [(size_t)NN * DD];     // s0 = x@W+b
__device__ __align__(16) float  g_s1[(size_t)NN * DD];     // s1
__device__ __align__(16) float2 g_edges[(size_t)NADJ * EE]; // packed (col,val)
__device__ int g_cnt   [NADJ * NN];
__device__ int g_fill  [NADJ * NN];
__device__ int g_rowptr[NADJ * (NN + 1)];

// ---------------- CSR build ------------------------------------------------
__global__ void zero_cnt_kernel() {
    int i = blockIdx.x * blockDim.x + threadIdx.x;
    if (i < NADJ * NN) g_cnt[i] = 0;
}

__global__ void hist_kernel(const int* __restrict__ rows) {
    int e = blockIdx.x * blockDim.x + threadIdx.x;
    int a = blockIdx.y;
    if (e < EE) atomicAdd(&g_cnt[a * NN + rows[(size_t)a * EE + e]], 1);
}

// one block per adjacency: chunked block-exclusive scan of counts -> rowptr/fill
__global__ void scan_kernel() {
    int a    = blockIdx.x;
    int tid  = threadIdx.x;
    int lane = tid & 31, wid = tid >> 5;
    __shared__ int wsum[32];
    __shared__ int s_tot;
    int running = 0;
    for (int base = 0; base < NN; base += 1024) {
        int idx = base + tid;
        int v = (idx < NN) ? g_cnt[a * NN + idx] : 0;
        int inc = v;
        #pragma unroll
        for (int d = 1; d < 32; d <<= 1) {
            int y = __shfl_up_sync(0xffffffffu, inc, d);
            if (lane >= d) inc += y;
        }
        if (lane == 31) wsum[wid] = inc;
        __syncthreads();
        if (wid == 0) {
            int w = wsum[lane];
            #pragma unroll
            for (int d = 1; d < 32; d <<= 1) {
                int y = __shfl_up_sync(0xffffffffu, w, d);
                if (lane >= d) w += y;
            }
            wsum[lane] = w;
            if (lane == 31) s_tot = w;
        }
        __syncthreads();
        int off  = (wid > 0) ? wsum[wid - 1] : 0;
        int excl = running + off + inc - v;
        if (idx < NN) {
            g_rowptr[a * (NN + 1) + idx] = excl;
            g_fill  [a * NN + idx]       = excl;
        }
        running += s_tot;
        __syncthreads();
    }
    if (tid == 0) g_rowptr[a * (NN + 1) + NN] = running;
}

__global__ void scatter_kernel(const int* __restrict__ rows,
                               const int* __restrict__ cols,
                               const float* __restrict__ vals) {
    int e = blockIdx.x * blockDim.x + threadIdx.x;
    int a = blockIdx.y;
    if (e >= EE) return;
    size_t idx = (size_t)a * EE + e;
    int   r = rows[idx];
    int   c = cols[idx];
    float v = vals[idx];
    int   p = atomicAdd(&g_fill[a * NN + r], 1);
    g_edges[(size_t)a * EE + p] = make_float2(__int_as_float(c), v);
}

// ---------------- GEMM: h = x @ W + b  (64x64 tile, 4x4 register blocking) -
__global__ void gemm_kernel(const float* __restrict__ x,
                            const float* __restrict__ Wm,
                            const float* __restrict__ b) {
    __shared__ float4 Ws4[64 * 16];
    __shared__ float  Xs[64 * 65];
    int tid = threadIdx.x;                 // 256 threads
    for (int i = tid; i < 64 * 16; i += 256) Ws4[i] = ((const float4*)Wm)[i];
    int rowBase = blockIdx.x * 64;
    for (int i = tid; i < 1024; i += 256) {
        int r = i >> 4, c4 = i & 15;
        int grow = rowBase + r;
        float4 v = make_float4(0.f, 0.f, 0.f, 0.f);
        if (grow < NN) v = ((const float4*)x)[(size_t)grow * 16 + c4];
        int o = r * 65 + c4 * 4;
        Xs[o] = v.x; Xs[o + 1] = v.y; Xs[o + 2] = v.z; Xs[o + 3] = v.w;
    }
    __syncthreads();
    int tx = tid & 15, ty = tid >> 4;
    float4 a0 = make_float4(0.f,0.f,0.f,0.f), a1 = a0, a2 = a0, a3 = a0;
    #pragma unroll 8
    for (int k = 0; k < 64; k++) {
        float4 wv = Ws4[k * 16 + tx];
        float x0 = Xs[(ty * 4 + 0) * 65 + k];
        float x1 = Xs[(ty * 4 + 1) * 65 + k];
        float x2 = Xs[(ty * 4 + 2) * 65 + k];
        float x3 = Xs[(ty * 4 + 3) * 65 + k];
        a0.x += x0 * wv.x; a0.y += x0 * wv.y; a0.z += x0 * wv.z; a0.w += x0 * wv.w;
        a1.x += x1 * wv.x; a1.y += x1 * wv.y; a1.z += x1 * wv.z; a1.w += x1 * wv.w;
        a2.x += x2 * wv.x; a2.y += x2 * wv.y; a2.z += x2 * wv.z; a2.w += x2 * wv.w;
        a3.x += x3 * wv.x; a3.y += x3 * wv.y; a3.z += x3 * wv.z; a3.w += x3 * wv.w;
    }
    float4 bv = ((const float4*)b)[tx];
    float4 outs[4] = {a0, a1, a2, a3};
    int r0 = rowBase + ty * 4;
    #pragma unroll
    for (int i = 0; i < 4; i++) {
        int r = r0 + i;
        if (r < NN) {
            float4 o = outs[i];
            o.x += bv.x; o.y += bv.y; o.z += bv.z; o.w += bv.w;
            ((float4*)g_h)[(size_t)r * 16 + tx] = o;
        }
    }
}

// ---------------- gather SpMM core -----------------------------------------
// Warp owns one output row; lane l accumulates columns 2l, 2l+1.
__device__ __forceinline__ void accum_lists(int a, int r,
                                            const float2* __restrict__ src2,
                                            int lane, float& ax, float& ay) {
    const float2* __restrict__ ed = g_edges + (size_t)a * EE;
    int beg = __ldg(&g_rowptr[a * (NN + 1) + r]);
    int end = __ldg(&g_rowptr[a * (NN + 1) + r + 1]);
    int i = beg;
    for (; i + 4 <= end; i += 4) {
        float2 e0 = ed[i], e1 = ed[i + 1], e2 = ed[i + 2], e3 = ed[i + 3];
        float2 h0 = __ldg(src2 + (size_t)__float_as_int(e0.x) * 32 + lane);
        float2 h1 = __ldg(src2 + (size_t)__float_as_int(e1.x) * 32 + lane);
        float2 h2 = __ldg(src2 + (size_t)__float_as_int(e2.x) * 32 + lane);
        float2 h3 = __ldg(src2 + (size_t)__float_as_int(e3.x) * 32 + lane);
        ax += e0.y * h0.x; ay += e0.y * h0.y;
        ax += e1.y * h1.x; ay += e1.y * h1.y;
        ax += e2.y * h2.x; ay += e2.y * h2.y;
        ax += e3.y * h3.x; ay += e3.y * h3.y;
    }
    for (; i < end; i++) {
        float2 e  = ed[i];
        float2 hv = __ldg(src2 + (size_t)__float_as_int(e.x) * 32 + lane);
        ax += e.y * hv.x; ay += e.y * hv.y;
    }
}

// s1 = 0.5 * (A[seq00] + A[seq01]) @ h
__global__ void spmm_mid_kernel(const int* __restrict__ idxes_seq) {
    int w    = (blockIdx.x * blockDim.x + threadIdx.x) >> 5;
    int lane = threadIdx.x & 31;
    if (w >= NN) return;
    int a0 = idxes_seq[0], a1 = idxes_seq[1];
    const float2* h2 = (const float2*)g_h;
    float ax = 0.f, ay = 0.f;
    accum_lists(a0, w, h2, lane, ax, ay);
    accum_lists(a1, w, h2, lane, ax, ay);
    ((float2*)g_s1)[(size_t)w * 32 + lane] = make_float2(0.5f * ax, 0.5f * ay);
}

// s2 = 0.5*((A[seq10]+A[seq11])@s1 + (A[res0]+A[res1])@h); LN; exact GELU
__global__ void final_kernel(const int* __restrict__ idxes_seq,
                             const int* __restrict__ idxes_res,
                             const float* __restrict__ gamma,
                             const float* __restrict__ beta,
                             float* __restrict__ out) {
    int w    = (blockIdx.x * blockDim.x + threadIdx.x) >> 5;
    int lane = threadIdx.x & 31;
    if (w >= NN) return;
    const float2* s1_2 = (const float2*)g_s1;
    const float2* h2   = (const float2*)g_h;
    float ax = 0.f, ay = 0.f;
    accum_lists(idxes_seq[2], w, s1_2, lane, ax, ay);
    accum_lists(idxes_seq[3], w, s1_2, lane, ax, ay);
    accum_lists(idxes_res[0], w, h2,   lane, ax, ay);
    accum_lists(idxes_res[1], w, h2,   lane, ax, ay);
    ax *= 0.5f; ay *= 0.5f;

    float s  = ax + ay;
    float ss = ax * ax + ay * ay;
    #pragma unroll
    for (int d = 16; d; d >>= 1) {
        s  += __shfl_xor_sync(0xffffffffu, s,  d);
        ss += __shfl_xor_sync(0xffffffffu, ss, d);
    }
    float mu   = s * (1.0f / 64.0f);
    float var  = ss * (1.0f / 64.0f) - mu * mu;
    float rstd = rsqrtf(var + 1e-5f);

    float2 g2 = ((const float2*)gamma)[lane];
    float2 b2 = ((const float2*)beta)[lane];
    float y0 = (ax - mu) * rstd * g2.x + b2.x;
    float y1 = (ay - mu) * rstd * g2.y + b2.y;
    y0 = 0.5f * y0 * (1.0f + erff(y0 * 0.70710678118654752f));
    y1 = 0.5f * y1 * (1.0f + erff(y1 * 0.70710678118654752f));
    ((float2*)out)[(size_t)w * 32 + lane] = make_float2(y0, y1);
}

// ---------------- launch ----------------------------------------------------
extern "C" void kernel_launch(void* const* d_in, const int* in_sizes, int n_in,
                              void* d_out, int out_size) {
    const float* x         = (const float*)d_in[0];
    const float* W         = (const float*)d_in[1];
    const float* b         = (const float*)d_in[2];
    const int*   rows      = (const int*)  d_in[3];
    const int*   cols      = (const int*)  d_in[4];
    const float* vals      = (const float*)d_in[5];
    const float* gamma     = (const float*)d_in[6];
    const float* beta      = (const float*)d_in[7];
    const int*   idxes_seq = (const int*)  d_in[8];
    const int*   idxes_res = (const int*)  d_in[9];
    float*       out       = (float*)d_out;

    zero_cnt_kernel<<<(NADJ * NN + 255) / 256, 256>>>();
    hist_kernel<<<dim3((EE + 255) / 256, NADJ), 256>>>(rows);
    scan_kernel<<<NADJ, 1024>>>();
    scatter_kernel<<<dim3((EE + 255) / 256, NADJ), 256>>>(rows, cols, vals);
    gemm_kernel<<<(NN + 63) / 64, 256>>>(x, W, b);

    // 1 warp per row: 100000 warps / 8 warps per block
    spmm_mid_kernel<<<(NN + 7) / 8, 256>>>(idxes_seq);
    final_kernel<<<(NN + 7) / 8, 256>>>(idxes_seq, idxes_res, gamma, beta, out);
}

// round 2
// speedup vs baseline: 1.3020x; 1.3020x over previous
#include <cuda_runtime.h>
#include <cuda_fp16.h>

#define NN   100000
#define EE   1600000
#define NADJ 4
#define DD   64

// ---------------- device scratch (static globals; no allocs allowed) ------
__device__ __align__(16) __half2 g_h [(size_t)NN * 32];    // s0 = x@W+b (fp16 storage)
__device__ __align__(16) __half2 g_s1[(size_t)NN * 32];    // s1 (fp16 storage)
__device__ __align__(16) float2  g_edges[(size_t)NADJ * EE]; // packed (col,val)
__device__ int g_cnt   [NADJ * NN];
__device__ int g_fill  [NADJ * NN];
__device__ int g_rowptr[NADJ * (NN + 1)];
__device__ int g_used  [NADJ];

// ---------------- used-adjacency mask --------------------------------------
__global__ void mask_kernel(const int* __restrict__ idxes_seq,
                            const int* __restrict__ idxes_res) {
    if (threadIdx.x == 0) {
        int m[NADJ];
        #pragma unroll
        for (int i = 0; i < NADJ; i++) m[i] = 0;
        #pragma unroll
        for (int i = 0; i < 4; i++) m[idxes_seq[i]] = 1;
        #pragma unroll
        for (int i = 0; i < 2; i++) m[idxes_res[i]] = 1;
        #pragma unroll
        for (int i = 0; i < NADJ; i++) g_used[i] = m[i];
    }
}

// ---------------- CSR build ------------------------------------------------
__global__ void zero_cnt_kernel() {
    int i = blockIdx.x * blockDim.x + threadIdx.x;
    if (i < NADJ * NN) g_cnt[i] = 0;
}

__global__ void hist_kernel(const int* __restrict__ rows) {
    int a = blockIdx.y;
    if (!g_used[a]) return;
    int e = blockIdx.x * blockDim.x + threadIdx.x;
    if (e < EE) atomicAdd(&g_cnt[a * NN + rows[(size_t)a * EE + e]], 1);
}

// one block per adjacency: chunked block-exclusive scan of counts -> rowptr/fill
__global__ void scan_kernel() {
    int a = blockIdx.x;
    if (!g_used[a]) return;
    int tid  = threadIdx.x;
    int lane = tid & 31, wid = tid >> 5;
    __shared__ int wsum[32];
    __shared__ int s_tot;
    int running = 0;
    for (int base = 0; base < NN; base += 1024) {
        int idx = base + tid;
        int v = (idx < NN) ? g_cnt[a * NN + idx] : 0;
        int inc = v;
        #pragma unroll
        for (int d = 1; d < 32; d <<= 1) {
            int y = __shfl_up_sync(0xffffffffu, inc, d);
            if (lane >= d) inc += y;
        }
        if (lane == 31) wsum[wid] = inc;
        __syncthreads();
        if (wid == 0) {
            int w = wsum[lane];
            #pragma unroll
            for (int d = 1; d < 32; d <<= 1) {
                int y = __shfl_up_sync(0xffffffffu, w, d);
                if (lane >= d) w += y;
            }
            wsum[lane] = w;
            if (lane == 31) s_tot = w;
        }
        __syncthreads();
        int off  = (wid > 0) ? wsum[wid - 1] : 0;
        int excl = running + off + inc - v;
        if (idx < NN) {
            g_rowptr[a * (NN + 1) + idx] = excl;
            g_fill  [a * NN + idx]       = excl;
        }
        running += s_tot;
        __syncthreads();
    }
    if (tid == 0) g_rowptr[a * (NN + 1) + NN] = running;
}

__global__ void scatter_kernel(const int* __restrict__ rows,
                               const int* __restrict__ cols,
                               const float* __restrict__ vals) {
    int a = blockIdx.y;
    if (!g_used[a]) return;
    int e = blockIdx.x * blockDim.x + threadIdx.x;
    if (e >= EE) return;
    size_t idx = (size_t)a * EE + e;
    int   r = rows[idx];
    int   c = cols[idx];
    float v = vals[idx];
    int   p = atomicAdd(&g_fill[a * NN + r], 1);
    g_edges[(size_t)a * EE + p] = make_float2(__int_as_float(c), v);
}

// ---------------- GEMM: h = x @ W + b  (64x64 tile, 4x4 register blocking) -
__global__ void gemm_kernel(const float* __restrict__ x,
                            const float* __restrict__ Wm,
                            const float* __restrict__ b) {
    __shared__ float4 Ws4[64 * 16];
    __shared__ float  Xs[64 * 65];
    int tid = threadIdx.x;                 // 256 threads
    for (int i = tid; i < 64 * 16; i += 256) Ws4[i] = ((const float4*)Wm)[i];
    int rowBase = blockIdx.x * 64;
    for (int i = tid; i < 1024; i += 256) {
        int r = i >> 4, c4 = i & 15;
        int grow = rowBase + r;
        float4 v = make_float4(0.f, 0.f, 0.f, 0.f);
        if (grow < NN) v = ((const float4*)x)[(size_t)grow * 16 + c4];
        int o = r * 65 + c4 * 4;
        Xs[o] = v.x; Xs[o + 1] = v.y; Xs[o + 2] = v.z; Xs[o + 3] = v.w;
    }
    __syncthreads();
    int tx = tid & 15, ty = tid >> 4;
    float4 a0 = make_float4(0.f,0.f,0.f,0.f), a1 = a0, a2 = a0, a3 = a0;
    #pragma unroll 8
    for (int k = 0; k < 64; k++) {
        float4 wv = Ws4[k * 16 + tx];
        float x0 = Xs[(ty * 4 + 0) * 65 + k];
        float x1 = Xs[(ty * 4 + 1) * 65 + k];
        float x2 = Xs[(ty * 4 + 2) * 65 + k];
        float x3 = Xs[(ty * 4 + 3) * 65 + k];
        a0.x += x0 * wv.x; a0.y += x0 * wv.y; a0.z += x0 * wv.z; a0.w += x0 * wv.w;
        a1.x += x1 * wv.x; a1.y += x1 * wv.y; a1.z += x1 * wv.z; a1.w += x1 * wv.w;
        a2.x += x2 * wv.x; a2.y += x2 * wv.y; a2.z += x2 * wv.z; a2.w += x2 * wv.w;
        a3.x += x3 * wv.x; a3.y += x3 * wv.y; a3.z += x3 * wv.z; a3.w += x3 * wv.w;
    }
    float4 bv = ((const float4*)b)[tx];
    float4 outs[4] = {a0, a1, a2, a3};
    int r0 = rowBase + ty * 4;
    #pragma unroll
    for (int i = 0; i < 4; i++) {
        int r = r0 + i;
        if (r < NN) {
            float4 o = outs[i];
            o.x += bv.x; o.y += bv.y; o.z += bv.z; o.w += bv.w;
            __half2 p0 = __floats2half2_rn(o.x, o.y);
            __half2 p1 = __floats2half2_rn(o.z, o.w);
            // cols 4tx..4tx+3 -> half2 slots 2tx, 2tx+1 : one 8B store
            __half2 pk[2] = {p0, p1};
            ((uint2*)g_h)[(size_t)r * 16 + tx] = *(uint2*)pk;
        }
    }
}

// ---------------- gather SpMM core -----------------------------------------
// Warp owns one output row; lane l accumulates columns 2l, 2l+1 (one half2).
__device__ __forceinline__ void accum_lists(int a, int r,
                                            const __half2* __restrict__ src,
                                            int lane, float& ax, float& ay) {
    const float2* __restrict__ ed = g_edges + (size_t)a * EE;
    int beg = __ldg(&g_rowptr[a * (NN + 1) + r]);
    int end = __ldg(&g_rowptr[a * (NN + 1) + r + 1]);
    int i = beg;
    for (; i + 4 <= end; i += 4) {
        float2 e0 = ed[i], e1 = ed[i + 1], e2 = ed[i + 2], e3 = ed[i + 3];
        float2 h0 = __half22float2(__ldg(src + (size_t)__float_as_int(e0.x) * 32 + lane));
        float2 h1 = __half22float2(__ldg(src + (size_t)__float_as_int(e1.x) * 32 + lane));
        float2 h2 = __half22float2(__ldg(src + (size_t)__float_as_int(e2.x) * 32 + lane));
        float2 h3 = __half22float2(__ldg(src + (size_t)__float_as_int(e3.x) * 32 + lane));
        ax += e0.y * h0.x; ay += e0.y * h0.y;
        ax += e1.y * h1.x; ay += e1.y * h1.y;
        ax += e2.y * h2.x; ay += e2.y * h2.y;
        ax += e3.y * h3.x; ay += e3.y * h3.y;
    }
    for (; i < end; i++) {
        float2 e  = ed[i];
        float2 hv = __half22float2(__ldg(src + (size_t)__float_as_int(e.x) * 32 + lane));
        ax += e.y * hv.x; ay += e.y * hv.y;
    }
}

// s1 = 0.5 * (A[seq00] + A[seq01]) @ h
__global__ void spmm_mid_kernel(const int* __restrict__ idxes_seq) {
    int w    = (blockIdx.x * blockDim.x + threadIdx.x) >> 5;
    int lane = threadIdx.x & 31;
    if (w >= NN) return;
    int a0 = idxes_seq[0], a1 = idxes_seq[1];
    float ax = 0.f, ay = 0.f;
    accum_lists(a0, w, g_h, lane, ax, ay);
    accum_lists(a1, w, g_h, lane, ax, ay);
    g_s1[(size_t)w * 32 + lane] = __floats2half2_rn(0.5f * ax, 0.5f * ay);
}

// s2 = 0.5*((A[seq10]+A[seq11])@s1 + (A[res0]+A[res1])@h); LN; exact GELU
__global__ void final_kernel(const int* __restrict__ idxes_seq,
                             const int* __restrict__ idxes_res,
                             const float* __restrict__ gamma,
                             const float* __restrict__ beta,
                             float* __restrict__ out) {
    int w    = (blockIdx.x * blockDim.x + threadIdx.x) >> 5;
    int lane = threadIdx.x & 31;
    if (w >= NN) return;
    float ax = 0.f, ay = 0.f;
    accum_lists(idxes_seq[2], w, g_s1, lane, ax, ay);
    accum_lists(idxes_seq[3], w, g_s1, lane, ax, ay);
    accum_lists(idxes_res[0], w, g_h,  lane, ax, ay);
    accum_lists(idxes_res[1], w, g_h,  lane, ax, ay);
    ax *= 0.5f; ay *= 0.5f;

    float s  = ax + ay;
    float ss = ax * ax + ay * ay;
    #pragma unroll
    for (int d = 16; d; d >>= 1) {
        s  += __shfl_xor_sync(0xffffffffu, s,  d);
        ss += __shfl_xor_sync(0xffffffffu, ss, d);
    }
    float mu   = s * (1.0f / 64.0f);
    float var  = ss * (1.0f / 64.0f) - mu * mu;
    float rstd = rsqrtf(var + 1e-5f);

    float2 g2 = ((const float2*)gamma)[lane];
    float2 b2 = ((const float2*)beta)[lane];
    float y0 = (ax - mu) * rstd * g2.x + b2.x;
    float y1 = (ay - mu) * rstd * g2.y + b2.y;
    y0 = 0.5f * y0 * (1.0f + erff(y0 * 0.70710678118654752f));
    y1 = 0.5f * y1 * (1.0f + erff(y1 * 0.70710678118654752f));
    ((float2*)out)[(size_t)w * 32 + lane] = make_float2(y0, y1);
}

// ---------------- launch ----------------------------------------------------
extern "C" void kernel_launch(void* const* d_in, const int* in_sizes, int n_in,
                              void* d_out, int out_size) {
    const float* x         = (const float*)d_in[0];
    const float* W         = (const float*)d_in[1];
    const float* b         = (const float*)d_in[2];
    const int*   rows      = (const int*)  d_in[3];
    const int*   cols      = (const int*)  d_in[4];
    const float* vals      = (const float*)d_in[5];
    const float* gamma     = (const float*)d_in[6];
    const float* beta      = (const float*)d_in[7];
    const int*   idxes_seq = (const int*)  d_in[8];
    const int*   idxes_res = (const int*)  d_in[9];
    float*       out       = (float*)d_out;

    mask_kernel<<<1, 32>>>(idxes_seq, idxes_res);
    zero_cnt_kernel<<<(NADJ * NN + 255) / 256, 256>>>();
    hist_kernel<<<dim3((EE + 255) / 256, NADJ), 256>>>(rows);
    scan_kernel<<<NADJ, 1024>>>();
    scatter_kernel<<<dim3((EE + 255) / 256, NADJ), 256>>>(rows, cols, vals);
    gemm_kernel<<<(NN + 63) / 64, 256>>>(x, W, b);

    // 1 warp per row: 100000 warps / 8 warps per block
    spmm_mid_kernel<<<(NN + 7) / 8, 256>>>(idxes_seq);
    final_kernel<<<(NN + 7) / 8, 256>>>(idxes_seq, idxes_res, gamma, beta, out);
}

// round 4
// speedup vs baseline: 1.5892x; 1.2206x over previous
#include <cuda_runtime.h>
#include <cuda_fp16.h>

#define NN   100000
#define EE   1600000
#define NADJ 4
#define DD   64

#define SCAN_TPB   512
#define SCAN_ITEMS 8
#define SCAN_CHUNK (SCAN_TPB * SCAN_ITEMS)              // 4096
#define SCAN_NBLK  ((NN + SCAN_CHUNK - 1) / SCAN_CHUNK) // 25

// ---------------- device scratch (static globals; no allocs allowed) ------
__device__ __align__(16) __half2 g_h [(size_t)NN * 32];    // s0 = x@W+b (fp16 storage)
__device__ __align__(16) __half2 g_s1[(size_t)NN * 32];    // s1 (fp16 storage)
__device__ __align__(16) float2  g_edges[(size_t)NADJ * EE]; // packed (col,val)
__device__ int g_cnt   [NADJ * NN];
__device__ int g_fill  [NADJ * NN];
__device__ int g_rowptr[NADJ * (NN + 1)];
__device__ int g_used  [NADJ];
__device__ int g_bsum  [NADJ * SCAN_NBLK];
__device__ int g_boff  [NADJ * SCAN_NBLK];

// ---------------- used-adjacency mask --------------------------------------
__global__ void mask_kernel(const int* __restrict__ idxes_seq,
                            const int* __restrict__ idxes_res) {
    if (threadIdx.x == 0) {
        int m[NADJ];
        #pragma unroll
        for (int i = 0; i < NADJ; i++) m[i] = 0;
        #pragma unroll
        for (int i = 0; i < 4; i++) m[idxes_seq[i]] = 1;
        #pragma unroll
        for (int i = 0; i < 2; i++) m[idxes_res[i]] = 1;
        #pragma unroll
        for (int i = 0; i < NADJ; i++) g_used[i] = m[i];
    }
}

// ---------------- CSR build ------------------------------------------------
__global__ void zero_cnt_kernel() {
    int i = blockIdx.x * blockDim.x + threadIdx.x;
    if (i < NADJ * NN) g_cnt[i] = 0;
}

__global__ void hist_kernel(const int* __restrict__ rows) {
    int a = blockIdx.y;
    if (!g_used[a]) return;
    int e = blockIdx.x * blockDim.x + threadIdx.x;
    if (e < EE) atomicAdd(&g_cnt[a * NN + rows[(size_t)a * EE + e]], 1);
}

// Phase 1: block-local exclusive scan of counts; block totals -> g_bsum.
__global__ void scan_local_kernel() {
    int a = blockIdx.y;
    if (!g_used[a]) return;
    int blk  = blockIdx.x;
    int tid  = threadIdx.x;
    int lane = tid & 31, wid = tid >> 5;          // 16 warps
    __shared__ int wsum[16];
    __shared__ int s_warp_off[16];

    int idx0 = blk * SCAN_CHUNK + tid * SCAN_ITEMS;
    int v[SCAN_ITEMS];
    int sum = 0;
    #pragma unroll
    for (int i = 0; i < SCAN_ITEMS; i++) {
        int idx = idx0 + i;
        int c = (idx < NN) ? g_cnt[a * NN + idx] : 0;
        v[i] = sum;          // exclusive within thread
        sum += c;
    }
    // warp inclusive scan of per-thread sums (all 32 lanes active)
    int inc = sum;
    #pragma unroll
    for (int d = 1; d < 32; d <<= 1) {
        int y = __shfl_up_sync(0xffffffffu, inc, d);
        if (lane >= d) inc += y;
    }
    if (lane == 31) wsum[wid] = inc;
    __syncthreads();
    // inter-warp scan: WHOLE warp 0 participates (lanes >=16 carry 0)
    if (wid == 0) {
        int v0 = (lane < 16) ? wsum[lane] : 0;
        int w = v0;
        #pragma unroll
        for (int d = 1; d < 32; d <<= 1) {
            int y = __shfl_up_sync(0xffffffffu, w, d);
            if (lane >= d) w += y;
        }
        if (lane < 16) s_warp_off[lane] = w - v0;     // exclusive warp offsets
        if (lane == 15) g_bsum[a * SCAN_NBLK + blk] = w;  // block total
    }
    __syncthreads();
    int toff = s_warp_off[wid] + (inc - sum);  // exclusive offset of this thread
    #pragma unroll
    for (int i = 0; i < SCAN_ITEMS; i++) {
        int idx = idx0 + i;
        if (idx < NN) g_rowptr[a * (NN + 1) + idx] = toff + v[i];
    }
}

// Phase 2: one warp per adjacency scans the 25 block totals.
__global__ void scan_bsum_kernel() {
    int a = blockIdx.x;
    if (!g_used[a]) return;
    int lane = threadIdx.x;
    int v = (lane < SCAN_NBLK) ? g_bsum[a * SCAN_NBLK + lane] : 0;
    int inc = v;
    #pragma unroll
    for (int d = 1; d < 32; d <<= 1) {
        int y = __shfl_up_sync(0xffffffffu, inc, d);
        if (lane >= d) inc += y;
    }
    if (lane < SCAN_NBLK) g_boff[a * SCAN_NBLK + lane] = inc - v;
    if (lane == 31) g_rowptr[a * (NN + 1) + NN] = inc;  // total nnz (== EE)
}

// Phase 3: add block offsets; emit final rowptr and fill cursors.
__global__ void scan_add_kernel() {
    int a = blockIdx.y;
    if (!g_used[a]) return;
    int blk = blockIdx.x;
    int off = g_boff[a * SCAN_NBLK + blk];
    int idx0 = blk * SCAN_CHUNK + threadIdx.x * SCAN_ITEMS;
    #pragma unroll
    for (int i = 0; i < SCAN_ITEMS; i++) {
        int idx = idx0 + i;
        if (idx < NN) {
            int p = g_rowptr[a * (NN + 1) + idx] + off;
            g_rowptr[a * (NN + 1) + idx] = p;
            g_fill  [a * NN + idx]       = p;
        }
    }
}

__global__ void scatter_kernel(const int* __restrict__ rows,
                               const int* __restrict__ cols,
                               const float* __restrict__ vals) {
    int a = blockIdx.y;
    if (!g_used[a]) return;
    int e = blockIdx.x * blockDim.x + threadIdx.x;
    if (e >= EE) return;
    size_t idx = (size_t)a * EE + e;
    int   r = rows[idx];
    int   c = cols[idx];
    float v = vals[idx];
    int   p = atomicAdd(&g_fill[a * NN + r], 1);
    g_edges[(size_t)a * EE + p] = make_float2(__int_as_float(c), v);
}

// ---------------- GEMM: h = x @ W + b  (64x64 tile, 4x4 register blocking) -
__global__ void gemm_kernel(const float* __restrict__ x,
                            const float* __restrict__ Wm,
                            const float* __restrict__ b) {
    __shared__ float4 Ws4[64 * 16];
    __shared__ float  Xs[64 * 65];
    int tid = threadIdx.x;                 // 256 threads
    for (int i = tid; i < 64 * 16; i += 256) Ws4[i] = ((const float4*)Wm)[i];
    int rowBase = blockIdx.x * 64;
    for (int i = tid; i < 1024; i += 256) {
        int r = i >> 4, c4 = i & 15;
        int grow = rowBase + r;
        float4 v = make_float4(0.f, 0.f, 0.f, 0.f);
        if (grow < NN) v = ((const float4*)x)[(size_t)grow * 16 + c4];
        int o = r * 65 + c4 * 4;
        Xs[o] = v.x; Xs[o + 1] = v.y; Xs[o + 2] = v.z; Xs[o + 3] = v.w;
    }
    __syncthreads();
    int tx = tid & 15, ty = tid >> 4;
    float4 a0 = make_float4(0.f,0.f,0.f,0.f), a1 = a0, a2 = a0, a3 = a0;
    #pragma unroll 8
    for (int k = 0; k < 64; k++) {
        float4 wv = Ws4[k * 16 + tx];
        float x0 = Xs[(ty * 4 + 0) * 65 + k];
        float x1 = Xs[(ty * 4 + 1) * 65 + k];
        float x2 = Xs[(ty * 4 + 2) * 65 + k];
        float x3 = Xs[(ty * 4 + 3) * 65 + k];
        a0.x += x0 * wv.x; a0.y += x0 * wv.y; a0.z += x0 * wv.z; a0.w += x0 * wv.w;
        a1.x += x1 * wv.x; a1.y += x1 * wv.y; a1.z += x1 * wv.z; a1.w += x1 * wv.w;
        a2.x += x2 * wv.x; a2.y += x2 * wv.y; a2.z += x2 * wv.z; a2.w += x2 * wv.w;
        a3.x += x3 * wv.x; a3.y += x3 * wv.y; a3.z += x3 * wv.z; a3.w += x3 * wv.w;
    }
    float4 bv = ((const float4*)b)[tx];
    float4 outs[4] = {a0, a1, a2, a3};
    int r0 = rowBase + ty * 4;
    #pragma unroll
    for (int i = 0; i < 4; i++) {
        int r = r0 + i;
        if (r < NN) {
            float4 o = outs[i];
            o.x += bv.x; o.y += bv.y; o.z += bv.z; o.w += bv.w;
            __half2 p0 = __floats2half2_rn(o.x, o.y);
            __half2 p1 = __floats2half2_rn(o.z, o.w);
            __half2 pk[2] = {p0, p1};
            ((uint2*)g_h)[(size_t)r * 16 + tx] = *(uint2*)pk;
        }
    }
}

// ---------------- gather SpMM core -----------------------------------------
// Warp owns one output row; lane l accumulates columns 2l, 2l+1 (one half2).
__device__ __forceinline__ void accum_lists(int a, int r,
                                            const __half2* __restrict__ src,
                                            int lane, float& ax, float& ay) {
    const float2* __restrict__ ed = g_edges + (size_t)a * EE;
    int beg = __ldg(&g_rowptr[a * (NN + 1) + r]);
    int end = __ldg(&g_rowptr[a * (NN + 1) + r + 1]);
    int i = beg;
    for (; i + 4 <= end; i += 4) {
        float2 e0 = ed[i], e1 = ed[i + 1], e2 = ed[i + 2], e3 = ed[i + 3];
        float2 h0 = __half22float2(__ldg(src + (size_t)__float_as_int(e0.x) * 32 + lane));
        float2 h1 = __half22float2(__ldg(src + (size_t)__float_as_int(e1.x) * 32 + lane));
        float2 h2 = __half22float2(__ldg(src + (size_t)__float_as_int(e2.x) * 32 + lane));
        float2 h3 = __half22float2(__ldg(src + (size_t)__float_as_int(e3.x) * 32 + lane));
        ax += e0.y * h0.x; ay += e0.y * h0.y;
        ax += e1.y * h1.x; ay += e1.y * h1.y;
        ax += e2.y * h2.x; ay += e2.y * h2.y;
        ax += e3.y * h3.x; ay += e3.y * h3.y;
    }
    for (; i < end; i++) {
        float2 e  = ed[i];
        float2 hv = __half22float2(__ldg(src + (size_t)__float_as_int(e.x) * 32 + lane));
        ax += e.y * hv.x; ay += e.y * hv.y;
    }
}

// s1 = 0.5 * (A[seq00] + A[seq01]) @ h
__global__ void spmm_mid_kernel(const int* __restrict__ idxes_seq) {
    int w    = (blockIdx.x * blockDim.x + threadIdx.x) >> 5;
    int lane = threadIdx.x & 31;
    if (w >= NN) return;
    int a0 = idxes_seq[0], a1 = idxes_seq[1];
    float ax = 0.f, ay = 0.f;
    accum_lists(a0, w, g_h, lane, ax, ay);
    accum_lists(a1, w, g_h, lane, ax, ay);
    g_s1[(size_t)w * 32 + lane] = __floats2half2_rn(0.5f * ax, 0.5f * ay);
}

// s2 = 0.5*((A[seq10]+A[seq11])@s1 + (A[res0]+A[res1])@h); LN; exact GELU
__global__ void final_kernel(const int* __restrict__ idxes_seq,
                             const int* __restrict__ idxes_res,
                             const float* __restrict__ gamma,
                             const float* __restrict__ beta,
                             float* __restrict__ out) {
    int w    = (blockIdx.x * blockDim.x + threadIdx.x) >> 5;
    int lane = threadIdx.x & 31;
    if (w >= NN) return;
    float ax = 0.f, ay = 0.f;
    accum_lists(idxes_seq[2], w, g_s1, lane, ax, ay);
    accum_lists(idxes_seq[3], w, g_s1, lane, ax, ay);
    accum_lists(idxes_res[0], w, g_h,  lane, ax, ay);
    accum_lists(idxes_res[1], w, g_h,  lane, ax, ay);
    ax *= 0.5f; ay *= 0.5f;

    float s  = ax + ay;
    float ss = ax * ax + ay * ay;
    #pragma unroll
    for (int d = 16; d; d >>= 1) {
        s  += __shfl_xor_sync(0xffffffffu, s,  d);
        ss += __shfl_xor_sync(0xffffffffu, ss, d);
    }
    float mu   = s * (1.0f / 64.0f);
    float var  = ss * (1.0f / 64.0f) - mu * mu;
    float rstd = rsqrtf(var + 1e-5f);

    float2 g2 = ((const float2*)gamma)[lane];
    float2 b2 = ((const float2*)beta)[lane];
    float y0 = (ax - mu) * rstd * g2.x + b2.x;
    float y1 = (ay - mu) * rstd * g2.y + b2.y;
    y0 = 0.5f * y0 * (1.0f + erff(y0 * 0.70710678118654752f));
    y1 = 0.5f * y1 * (1.0f + erff(y1 * 0.70710678118654752f));
    ((float2*)out)[(size_t)w * 32 + lane] = make_float2(y0, y1);
}

// ---------------- launch ----------------------------------------------------
extern "C" void kernel_launch(void* const* d_in, const int* in_sizes, int n_in,
                              void* d_out, int out_size) {
    const float* x         = (const float*)d_in[0];
    const float* W         = (const float*)d_in[1];
    const float* b         = (const float*)d_in[2];
    const int*   rows      = (const int*)  d_in[3];
    const int*   cols      = (const int*)  d_in[4];
    const float* vals      = (const float*)d_in[5];
    const float* gamma     = (const float*)d_in[6];
    const float* beta      = (const float*)d_in[7];
    const int*   idxes_seq = (const int*)  d_in[8];
    const int*   idxes_res = (const int*)  d_in[9];
    float*       out       = (float*)d_out;

    mask_kernel<<<1, 32>>>(idxes_seq, idxes_res);
    zero_cnt_kernel<<<(NADJ * NN + 255) / 256, 256>>>();
    hist_kernel<<<dim3((EE + 255) / 256, NADJ), 256>>>(rows);
    scan_local_kernel<<<dim3(SCAN_NBLK, NADJ), SCAN_TPB>>>();
    scan_bsum_kernel<<<NADJ, 32>>>();
    scan_add_kernel<<<dim3(SCAN_NBLK, NADJ), SCAN_TPB>>>();
    scatter_kernel<<<dim3((EE + 255) / 256, NADJ), 256>>>(rows, cols, vals);
    gemm_kernel<<<(NN + 63) / 64, 256>>>(x, W, b);

    // 1 warp per row: 100000 warps / 8 warps per block
    spmm_mid_kernel<<<(NN + 7) / 8, 256>>>(idxes_seq);
    final_kernel<<<(NN + 7) / 8, 256>>>(idxes_seq, idxes_res, gamma, beta, out);
}

// round 5
// speedup vs baseline: 1.8271x; 1.1497x over previous
#include <cuda_runtime.h>
#include <cuda_fp16.h>

#define NN   100000
#define EE   1600000
#define NADJ 4
#define DD   64

#define SCAN_TPB   512
#define SCAN_ITEMS 8
#define SCAN_CHUNK (SCAN_TPB * SCAN_ITEMS)              // 4096
#define SCAN_NBLK  ((NN + SCAN_CHUNK - 1) / SCAN_CHUNK) // 25

#define HIST_BLKX  ((EE + 255) / 256)                   // 6250
#define GEMM_BLKS  ((NN + 63) / 64)                     // 1563

// ---------------- device scratch (static globals; no allocs allowed) ------
__device__ __align__(16) __half2 g_h [(size_t)NN * 32];      // s0 (fp16 storage)
__device__ __align__(16) __half2 g_s1[(size_t)NN * 32];      // s1 (fp16 storage)
__device__ __align__(16) float2  g_edges[(size_t)NADJ * EE]; // packed (col,val)
__device__ int g_rank  [(size_t)NADJ * EE];
__device__ int g_cnt   [NADJ * NN];
__device__ int g_rowptr[NADJ * (NN + 1)];
__device__ int g_used  [NADJ];
__device__ int g_bsum  [NADJ * SCAN_NBLK];
__device__ int g_boff  [NADJ * SCAN_NBLK];

// ---------------- zero counts + used-adjacency mask ------------------------
__global__ void zero_mask_kernel(const int* __restrict__ idxes_seq,
                                 const int* __restrict__ idxes_res) {
    int i = blockIdx.x * blockDim.x + threadIdx.x;
    if (i < NADJ * NN) g_cnt[i] = 0;
    if (blockIdx.x == 0 && threadIdx.x == 0) {
        int m[NADJ];
        #pragma unroll
        for (int k = 0; k < NADJ; k++) m[k] = 0;
        #pragma unroll
        for (int k = 0; k < 4; k++) m[idxes_seq[k]] = 1;
        #pragma unroll
        for (int k = 0; k < 2; k++) m[idxes_res[k]] = 1;
        #pragma unroll
        for (int k = 0; k < NADJ; k++) g_used[k] = m[k];
    }
}

// ---------------- fused histogram(+rank) and GEMM --------------------------
// blockIdx.y in [0, NADJ): histogram for adjacency y (rank recorded).
// blockIdx.y == NADJ:      GEMM h = x@W + b (first GEMM_BLKS x-blocks).
__global__ void hist_gemm_kernel(const int* __restrict__ rows,
                                 const float* __restrict__ x,
                                 const float* __restrict__ Wm,
                                 const float* __restrict__ b) {
    __shared__ float4 Ws4[64 * 16];
    __shared__ float  Xs[64 * 65];
    int tid = threadIdx.x;

    if (blockIdx.y < NADJ) {
        int a = blockIdx.y;
        if (!g_used[a]) return;
        int e = blockIdx.x * blockDim.x + tid;
        if (e < EE) {
            int r = rows[(size_t)a * EE + e];
            int p = atomicAdd(&g_cnt[a * NN + r], 1);
            g_rank[(size_t)a * EE + e] = p;
        }
        return;
    }

    // ---- GEMM part ----
    if (blockIdx.x >= GEMM_BLKS) return;
    for (int i = tid; i < 64 * 16; i += 256) Ws4[i] = ((const float4*)Wm)[i];
    int rowBase = blockIdx.x * 64;
    for (int i = tid; i < 1024; i += 256) {
        int r = i >> 4, c4 = i & 15;
        int grow = rowBase + r;
        float4 v = make_float4(0.f, 0.f, 0.f, 0.f);
        if (grow < NN) v = ((const float4*)x)[(size_t)grow * 16 + c4];
        int o = r * 65 + c4 * 4;
        Xs[o] = v.x; Xs[o + 1] = v.y; Xs[o + 2] = v.z; Xs[o + 3] = v.w;
    }
    __syncthreads();
    int tx = tid & 15, ty = tid >> 4;
    float4 a0 = make_float4(0.f,0.f,0.f,0.f), a1 = a0, a2 = a0, a3 = a0;
    #pragma unroll 8
    for (int k = 0; k < 64; k++) {
        float4 wv = Ws4[k * 16 + tx];
        float x0 = Xs[(ty * 4 + 0) * 65 + k];
        float x1 = Xs[(ty * 4 + 1) * 65 + k];
        float x2 = Xs[(ty * 4 + 2) * 65 + k];
        float x3 = Xs[(ty * 4 + 3) * 65 + k];
        a0.x += x0 * wv.x; a0.y += x0 * wv.y; a0.z += x0 * wv.z; a0.w += x0 * wv.w;
        a1.x += x1 * wv.x; a1.y += x1 * wv.y; a1.z += x1 * wv.z; a1.w += x1 * wv.w;
        a2.x += x2 * wv.x; a2.y += x2 * wv.y; a2.z += x2 * wv.z; a2.w += x2 * wv.w;
        a3.x += x3 * wv.x; a3.y += x3 * wv.y; a3.z += x3 * wv.z; a3.w += x3 * wv.w;
    }
    float4 bv = ((const float4*)b)[tx];
    float4 outs[4] = {a0, a1, a2, a3};
    int r0 = rowBase + ty * 4;
    #pragma unroll
    for (int i = 0; i < 4; i++) {
        int r = r0 + i;
        if (r < NN) {
            float4 o = outs[i];
            o.x += bv.x; o.y += bv.y; o.z += bv.z; o.w += bv.w;
            __half2 p0 = __floats2half2_rn(o.x, o.y);
            __half2 p1 = __floats2half2_rn(o.z, o.w);
            __half2 pk[2] = {p0, p1};
            ((uint2*)g_h)[(size_t)r * 16 + tx] = *(uint2*)pk;
        }
    }
}

// ---------------- scan (3-phase) --------------------------------------------
__global__ void scan_local_kernel() {
    int a = blockIdx.y;
    if (!g_used[a]) return;
    int blk  = blockIdx.x;
    int tid  = threadIdx.x;
    int lane = tid & 31, wid = tid >> 5;          // 16 warps
    __shared__ int wsum[16];
    __shared__ int s_warp_off[16];

    int idx0 = blk * SCAN_CHUNK + tid * SCAN_ITEMS;
    int v[SCAN_ITEMS];
    int sum = 0;
    #pragma unroll
    for (int i = 0; i < SCAN_ITEMS; i++) {
        int idx = idx0 + i;
        int c = (idx < NN) ? g_cnt[a * NN + idx] : 0;
        v[i] = sum;
        sum += c;
    }
    int inc = sum;
    #pragma unroll
    for (int d = 1; d < 32; d <<= 1) {
        int y = __shfl_up_sync(0xffffffffu, inc, d);
        if (lane >= d) inc += y;
    }
    if (lane == 31) wsum[wid] = inc;
    __syncthreads();
    if (wid == 0) {
        int v0 = (lane < 16) ? wsum[lane] : 0;
        int w = v0;
        #pragma unroll
        for (int d = 1; d < 32; d <<= 1) {
            int y = __shfl_up_sync(0xffffffffu, w, d);
            if (lane >= d) w += y;
        }
        if (lane < 16) s_warp_off[lane] = w - v0;
        if (lane == 15) g_bsum[a * SCAN_NBLK + blk] = w;
    }
    __syncthreads();
    int toff = s_warp_off[wid] + (inc - sum);
    #pragma unroll
    for (int i = 0; i < SCAN_ITEMS; i++) {
        int idx = idx0 + i;
        if (idx < NN) g_rowptr[a * (NN + 1) + idx] = toff + v[i];
    }
}

__global__ void scan_bsum_kernel() {
    int a = blockIdx.x;
    if (!g_used[a]) return;
    int lane = threadIdx.x;
    int v = (lane < SCAN_NBLK) ? g_bsum[a * SCAN_NBLK + lane] : 0;
    int inc = v;
    #pragma unroll
    for (int d = 1; d < 32; d <<= 1) {
        int y = __shfl_up_sync(0xffffffffu, inc, d);
        if (lane >= d) inc += y;
    }
    if (lane < SCAN_NBLK) g_boff[a * SCAN_NBLK + lane] = inc - v;
    if (lane == 31) g_rowptr[a * (NN + 1) + NN] = inc;
}

__global__ void scan_add_kernel() {
    int a = blockIdx.y;
    if (!g_used[a]) return;
    int blk = blockIdx.x;
    int off = g_boff[a * SCAN_NBLK + blk];
    int idx0 = blk * SCAN_CHUNK + threadIdx.x * SCAN_ITEMS;
    #pragma unroll
    for (int i = 0; i < SCAN_ITEMS; i++) {
        int idx = idx0 + i;
        if (idx < NN) g_rowptr[a * (NN + 1) + idx] += off;
    }
}

// ---------------- scatter (no atomics: rank precomputed) --------------------
__global__ void scatter_kernel(const int* __restrict__ rows,
                               const int* __restrict__ cols,
                               const float* __restrict__ vals) {
    int a = blockIdx.y;
    if (!g_used[a]) return;
    int e = blockIdx.x * blockDim.x + threadIdx.x;
    if (e >= EE) return;
    size_t idx = (size_t)a * EE + e;
    int   r = rows[idx];
    int   c = cols[idx];
    float v = vals[idx];
    int   p = __ldg(&g_rowptr[a * (NN + 1) + r]) + g_rank[idx];
    g_edges[(size_t)a * EE + p] = make_float2(__int_as_float(c), v);
}

// ---------------- gather SpMM core ------------------------------------------
__device__ __forceinline__ void accum_lists(int a, int r,
                                            const __half2* __restrict__ src,
                                            int lane, float& ax, float& ay) {
    const float2* __restrict__ ed = g_edges + (size_t)a * EE;
    int beg = __ldg(&g_rowptr[a * (NN + 1) + r]);
    int end = __ldg(&g_rowptr[a * (NN + 1) + r + 1]);
    int i = beg;
    for (; i + 4 <= end; i += 4) {
        float2 e0 = ed[i], e1 = ed[i + 1], e2 = ed[i + 2], e3 = ed[i + 3];
        float2 h0 = __half22float2(__ldg(src + (size_t)__float_as_int(e0.x) * 32 + lane));
        float2 h1 = __half22float2(__ldg(src + (size_t)__float_as_int(e1.x) * 32 + lane));
        float2 h2 = __half22float2(__ldg(src + (size_t)__float_as_int(e2.x) * 32 + lane));
        float2 h3 = __half22float2(__ldg(src + (size_t)__float_as_int(e3.x) * 32 + lane));
        ax += e0.y * h0.x; ay += e0.y * h0.y;
        ax += e1.y * h1.x; ay += e1.y * h1.y;
        ax += e2.y * h2.x; ay += e2.y * h2.y;
        ax += e3.y * h3.x; ay += e3.y * h3.y;
    }
    for (; i < end; i++) {
        float2 e  = ed[i];
        float2 hv = __half22float2(__ldg(src + (size_t)__float_as_int(e.x) * 32 + lane));
        ax += e.y * hv.x; ay += e.y * hv.y;
    }
}

// op(src) = (spmm(a0,src)+spmm(a1,src))/2 ; if a0==a1 this equals spmm(a0,src)
__device__ __forceinline__ void op_pair(int a0, int a1, int r,
                                        const __half2* __restrict__ src,
                                        int lane, float& ox, float& oy) {
    float ax = 0.f, ay = 0.f;
    accum_lists(a0, r, src, lane, ax, ay);
    if (a0 != a1) {
        accum_lists(a1, r, src, lane, ax, ay);
        ax *= 0.5f; ay *= 0.5f;
    }
    ox += ax; oy += ay;
}

// s1 = op_seq0(h)
__global__ void spmm_mid_kernel(const int* __restrict__ idxes_seq) {
    int w    = (blockIdx.x * blockDim.x + threadIdx.x) >> 5;
    int lane = threadIdx.x & 31;
    if (w >= NN) return;
    float ax = 0.f, ay = 0.f;
    op_pair(idxes_seq[0], idxes_seq[1], w, g_h, lane, ax, ay);
    g_s1[(size_t)w * 32 + lane] = __floats2half2_rn(ax, ay);
}

// s2 = op_seq1(s1) + op_res(h); LN; exact GELU
__global__ void final_kernel(const int* __restrict__ idxes_seq,
                             const int* __restrict__ idxes_res,
                             const float* __restrict__ gamma,
                             const float* __restrict__ beta,
                             float* __restrict__ out) {
    int w    = (blockIdx.x * blockDim.x + threadIdx.x) >> 5;
    int lane = threadIdx.x & 31;
    if (w >= NN) return;
    float ax = 0.f, ay = 0.f;
    op_pair(idxes_seq[2], idxes_seq[3], w, g_s1, lane, ax, ay);
    op_pair(idxes_res[0], idxes_res[1], w, g_h,  lane, ax, ay);

    float s  = ax + ay;
    float ss = ax * ax + ay * ay;
    #pragma unroll
    for (int d = 16; d; d >>= 1) {
        s  += __shfl_xor_sync(0xffffffffu, s,  d);
        ss += __shfl_xor_sync(0xffffffffu, ss, d);
    }
    float mu   = s * (1.0f / 64.0f);
    float var  = ss * (1.0f / 64.0f) - mu * mu;
    float rstd = rsqrtf(var + 1e-5f);

    float2 g2 = ((const float2*)gamma)[lane];
    float2 b2 = ((const float2*)beta)[lane];
    float y0 = (ax - mu) * rstd * g2.x + b2.x;
    float y1 = (ay - mu) * rstd * g2.y + b2.y;
    y0 = 0.5f * y0 * (1.0f + erff(y0 * 0.70710678118654752f));
    y1 = 0.5f * y1 * (1.0f + erff(y1 * 0.70710678118654752f));
    ((float2*)out)[(size_t)w * 32 + lane] = make_float2(y0, y1);
}

// ---------------- launch -----------------------------------------------------
extern "C" void kernel_launch(void* const* d_in, const int* in_sizes, int n_in,
                              void* d_out, int out_size) {
    const float* x         = (const float*)d_in[0];
    const float* W         = (const float*)d_in[1];
    const float* b         = (const float*)d_in[2];
    const int*   rows      = (const int*)  d_in[3];
    const int*   cols      = (const int*)  d_in[4];
    const float* vals      = (const float*)d_in[5];
    const float* gamma     = (const float*)d_in[6];
    const float* beta      = (const float*)d_in[7];
    const int*   idxes_seq = (const int*)  d_in[8];
    const int*   idxes_res = (const int*)  d_in[9];
    float*       out       = (float*)d_out;

    zero_mask_kernel<<<(NADJ * NN + 255) / 256, 256>>>(idxes_seq, idxes_res);
    hist_gemm_kernel<<<dim3(HIST_BLKX, NADJ + 1), 256>>>(rows, x, W, b);
    scan_local_kernel<<<dim3(SCAN_NBLK, NADJ), SCAN_TPB>>>();
    scan_bsum_kernel<<<NADJ, 32>>>();
    scan_add_kernel<<<dim3(SCAN_NBLK, NADJ), SCAN_TPB>>>();
    scatter_kernel<<<dim3((EE + 255) / 256, NADJ), 256>>>(rows, cols, vals);

    spmm_mid_kernel<<<(NN + 7) / 8, 256>>>(idxes_seq);
    final_kernel<<<(NN + 7) / 8, 256>>>(idxes_seq, idxes_res, gamma, beta, out);
}